// round 1
// baseline (speedup 1.0000x reference)
#include <cuda_runtime.h>
#include <math.h>

#define BB 2
#define NSEQ 2048
#define DIMC 768
#define NH 12
#define DH 64
#define BHN (BB*NH)
#define MROWS (BB*NSEQ)
#define QSCALE 0.125f

// ---------------- scratch (static device globals; no allocation) -------------
__device__ float g_qkv[(size_t)MROWS * 3 * DIMC];          // 37.7 MB
__device__ float g_q[(size_t)BHN * NSEQ * DH];             // 12.6 MB
__device__ float g_k[(size_t)BHN * NSEQ * DH];
__device__ float g_v[(size_t)BHN * NSEQ * DH];
__device__ float g_att[(size_t)MROWS * DIMC];

// ---------------- SGEMM: C[m][n] = sum_k A[m][k] * W[n][k] (+bias) ----------
// 128x128 tile, BK=8, 256 threads, 8x8 microtile (split 4+4 fragments).
template<bool BIAS>
__global__ void __launch_bounds__(256) sgemm_nt(
    const float* __restrict__ A, const float* __restrict__ W,
    const float* __restrict__ bias, float* __restrict__ C,
    int Mdim, int Ndim, int Kdim)
{
    __shared__ float As[8][128];
    __shared__ float Bs[8][128];

    const int tid = threadIdx.x;
    const int tx = tid & 15;
    const int ty = tid >> 4;
    const int mtile = blockIdx.y * 128;
    const int ntile = blockIdx.x * 128;

    const int lr = tid >> 1;          // 0..127
    const int lc = (tid & 1) << 2;    // 0 or 4

    const float* Ap = A + (size_t)(mtile + lr) * Kdim + lc;
    const float* Wp = W + (size_t)(ntile + lr) * Kdim + lc;

    float acc[8][8];
#pragma unroll
    for (int i = 0; i < 8; i++)
#pragma unroll
        for (int j = 0; j < 8; j++) acc[i][j] = 0.f;

    for (int k0 = 0; k0 < Kdim; k0 += 8) {
        float4 av = *(const float4*)(Ap + k0);
        float4 wv = *(const float4*)(Wp + k0);
        __syncthreads();
        As[lc + 0][lr] = av.x; As[lc + 1][lr] = av.y;
        As[lc + 2][lr] = av.z; As[lc + 3][lr] = av.w;
        Bs[lc + 0][lr] = wv.x; Bs[lc + 1][lr] = wv.y;
        Bs[lc + 2][lr] = wv.z; Bs[lc + 3][lr] = wv.w;
        __syncthreads();
#pragma unroll
        for (int kk = 0; kk < 8; kk++) {
            float a[8], b[8];
            *(float4*)&a[0] = *(const float4*)&As[kk][ty * 4];
            *(float4*)&a[4] = *(const float4*)&As[kk][64 + ty * 4];
            *(float4*)&b[0] = *(const float4*)&Bs[kk][tx * 4];
            *(float4*)&b[4] = *(const float4*)&Bs[kk][64 + tx * 4];
#pragma unroll
            for (int i = 0; i < 8; i++)
#pragma unroll
                for (int j = 0; j < 8; j++)
                    acc[i][j] += a[i] * b[j];
        }
    }

#pragma unroll
    for (int i = 0; i < 8; i++) {
        int m = mtile + ((i < 4) ? (ty * 4 + i) : (64 + ty * 4 + i - 4));
#pragma unroll
        for (int jg = 0; jg < 2; jg++) {
            int n = ntile + jg * 64 + tx * 4;
            float4 v;
            v.x = acc[i][jg * 4 + 0];
            v.y = acc[i][jg * 4 + 1];
            v.z = acc[i][jg * 4 + 2];
            v.w = acc[i][jg * 4 + 3];
            if (BIAS) {
                v.x += bias[n + 0]; v.y += bias[n + 1];
                v.z += bias[n + 2]; v.w += bias[n + 3];
            }
            *(float4*)(C + (size_t)m * Ndim + n) = v;
        }
    }
}

// -------- fused rmsnorm + 3D RoPE + q-scale + [B,N,3,H,DH]->[BH,N,DH] -------
// One warp per (b,t,h); each lane handles the pair (2*lane, 2*lane+1).
__global__ void __launch_bounds__(256) prep_kernel(
    const float* __restrict__ qkv, const float* __restrict__ positions,
    const float* __restrict__ qn_w, const float* __restrict__ kn_w,
    float* __restrict__ qT, float* __restrict__ kT, float* __restrict__ vT)
{
    int gwarp = (blockIdx.x * blockDim.x + threadIdx.x) >> 5;
    int lane  = threadIdx.x & 31;
    if (gwarp >= MROWS * NH) return;
    int h = gwarp % NH;
    int m = gwarp / NH;          // m = b*NSEQ + t
    int b = m / NSEQ;
    int t = m % NSEQ;

    const float* row = qkv + (size_t)m * (3 * DIMC) + h * DH;
    float2 q = *(const float2*)(row + 2 * lane);
    float2 k = *(const float2*)(row + DIMC + 2 * lane);
    float2 v = *(const float2*)(row + 2 * DIMC + 2 * lane);

    float sq = q.x * q.x + q.y * q.y;
    float sk = k.x * k.x + k.y * k.y;
#pragma unroll
    for (int off = 16; off; off >>= 1) {
        sq += __shfl_xor_sync(0xffffffffu, sq, off);
        sk += __shfl_xor_sync(0xffffffffu, sk, off);
    }
    float rq = rsqrtf(sq * (1.0f / 64.0f) + 1e-6f);
    float rk = rsqrtf(sk * (1.0f / 64.0f) + 1e-6f);
    float2 wq = *(const float2*)(qn_w + 2 * lane);
    float2 wk = *(const float2*)(kn_w + 2 * lane);
    q.x *= rq * wq.x; q.y *= rq * wq.y;
    k.x *= rk * wk.x; k.y *= rk * wk.y;

    if (lane < 30) {                   // rope pairs: first 60 dims
        int p = lane / 10;             // which position component (0..2)
        int f = lane % 10;             // freq index
        float pos  = positions[(size_t)m * 3 + p];
        float freq = __expf(-0.92103403719761836f * (float)f);  // 10000^(-f/10)
        float ang  = pos * freq;
        float s, c;
        __sincosf(ang, &s, &c);
        float qe = q.x * c - q.y * s, qo = q.x * s + q.y * c;
        float ke = k.x * c - k.y * s, ko = k.x * s + k.y * c;
        q.x = qe; q.y = qo; k.x = ke; k.y = ko;
    }
    q.x *= QSCALE; q.y *= QSCALE;

    size_t o = ((size_t)(b * NH + h) * NSEQ + t) * DH + 2 * lane;
    *(float2*)(qT + o) = q;
    *(float2*)(kT + o) = k;
    *(float2*)(vT + o) = v;
}

// ---------------- flash-attention (fp32, online softmax) --------------------
// block = 256 threads, 64 queries x full key loop in 64-chunks.
#define SPITCH 68
__global__ void __launch_bounds__(256) attn_kernel(
    const float* __restrict__ qT, const float* __restrict__ kT,
    const float* __restrict__ vT, float* __restrict__ out)
{
    extern __shared__ float smn[];
    float* Qs = smn;
    float* Ks = smn + 64 * SPITCH;
    float* Vs = smn + 2 * 64 * SPITCH;
    float* Ps = smn + 3 * 64 * SPITCH;

    const int tid = threadIdx.x;
    const int tx = tid & 15;
    const int ty = tid >> 4;
    const int qt = blockIdx.x;
    const int bh = blockIdx.y;

    const float* qb = qT + ((size_t)bh * NSEQ + qt * 64) * DH;
#pragma unroll
    for (int rep = 0; rep < 4; rep++) {
        int r = rep * 16 + ty;
        *(float4*)&Qs[r * SPITCH + tx * 4] = *(const float4*)(qb + r * 64 + tx * 4);
    }

    float o[4][4];
    float mi[4], li[4];
#pragma unroll
    for (int r = 0; r < 4; r++) {
        mi[r] = -1e30f; li[r] = 0.f;
#pragma unroll
        for (int c = 0; c < 4; c++) o[r][c] = 0.f;
    }

    for (int kc = 0; kc < NSEQ / 64; kc++) {
        const float* kb = kT + ((size_t)bh * NSEQ + kc * 64) * DH;
        const float* vb = vT + ((size_t)bh * NSEQ + kc * 64) * DH;
        __syncthreads();   // protect Ks/Vs/Ps reuse (also publishes Qs on iter 0)
#pragma unroll
        for (int rep = 0; rep < 4; rep++) {
            int r = rep * 16 + ty;
            *(float4*)&Ks[r * SPITCH + tx * 4] = *(const float4*)(kb + r * 64 + tx * 4);
            *(float4*)&Vs[r * SPITCH + tx * 4] = *(const float4*)(vb + r * 64 + tx * 4);
        }
        __syncthreads();

        // S = Q @ K^T   (thread: 4 q-rows x 4 k-cols)
        float s[4][4];
#pragma unroll
        for (int r = 0; r < 4; r++)
#pragma unroll
            for (int c = 0; c < 4; c++) s[r][c] = 0.f;
#pragma unroll
        for (int d4 = 0; d4 < 16; d4++) {
            float4 a[4], bq[4];
#pragma unroll
            for (int r = 0; r < 4; r++)
                a[r] = *(const float4*)&Qs[(ty * 4 + r) * SPITCH + d4 * 4];
#pragma unroll
            for (int c = 0; c < 4; c++)
                bq[c] = *(const float4*)&Ks[(tx * 4 + c) * SPITCH + d4 * 4];
#pragma unroll
            for (int r = 0; r < 4; r++)
#pragma unroll
                for (int c = 0; c < 4; c++)
                    s[r][c] += a[r].x * bq[c].x + a[r].y * bq[c].y
                             + a[r].z * bq[c].z + a[r].w * bq[c].w;
        }

        // online softmax update
#pragma unroll
        for (int r = 0; r < 4; r++) {
            float lm = fmaxf(fmaxf(s[r][0], s[r][1]), fmaxf(s[r][2], s[r][3]));
#pragma unroll
            for (int off = 8; off; off >>= 1)
                lm = fmaxf(lm, __shfl_xor_sync(0xffffffffu, lm, off));
            float mn = fmaxf(mi[r], lm);
            float corr = __expf(mi[r] - mn);
            mi[r] = mn;
            float4 pv;
            pv.x = __expf(s[r][0] - mn);
            pv.y = __expf(s[r][1] - mn);
            pv.z = __expf(s[r][2] - mn);
            pv.w = __expf(s[r][3] - mn);
            *(float4*)&Ps[(ty * 4 + r) * SPITCH + tx * 4] = pv;
            float ps = pv.x + pv.y + pv.z + pv.w;
#pragma unroll
            for (int off = 8; off; off >>= 1)
                ps += __shfl_xor_sync(0xffffffffu, ps, off);
            li[r] = li[r] * corr + ps;
#pragma unroll
            for (int c = 0; c < 4; c++) o[r][c] *= corr;
        }
        __syncthreads();

        // O += P @ V   (thread: 4 q-rows x 4 d-cols)
#pragma unroll
        for (int k4 = 0; k4 < 16; k4++) {
            float pp[4][4];
#pragma unroll
            for (int r = 0; r < 4; r++)
                *(float4*)pp[r] = *(const float4*)&Ps[(ty * 4 + r) * SPITCH + k4 * 4];
#pragma unroll
            for (int j = 0; j < 4; j++) {
                float4 vv = *(const float4*)&Vs[(k4 * 4 + j) * SPITCH + tx * 4];
#pragma unroll
                for (int r = 0; r < 4; r++) {
                    o[r][0] += pp[r][j] * vv.x;
                    o[r][1] += pp[r][j] * vv.y;
                    o[r][2] += pp[r][j] * vv.z;
                    o[r][3] += pp[r][j] * vv.w;
                }
            }
        }
    }

    // epilogue: write [m, h*64+d]
    const int b = bh / NH, h = bh % NH;
#pragma unroll
    for (int r = 0; r < 4; r++) {
        float inv = 1.0f / li[r];
        int qrow = qt * 64 + ty * 4 + r;
        float4 v;
        v.x = o[r][0] * inv; v.y = o[r][1] * inv;
        v.z = o[r][2] * inv; v.w = o[r][3] * inv;
        *(float4*)(out + (size_t)(b * NSEQ + qrow) * DIMC + h * DH + tx * 4) = v;
    }
}

// ---------------- launch --------------------------------------------------
extern "C" void kernel_launch(void* const* d_in, const int* in_sizes, int n_in,
                              void* d_out, int out_size)
{
    (void)in_sizes; (void)n_in; (void)out_size;
    const float* x         = (const float*)d_in[0];
    const float* positions = (const float*)d_in[1];
    const float* qkv_w     = (const float*)d_in[2];
    const float* proj_w    = (const float*)d_in[3];
    const float* proj_b    = (const float*)d_in[4];
    const float* qn_w      = (const float*)d_in[5];
    const float* kn_w      = (const float*)d_in[6];
    float* out = (float*)d_out;

    float *qkv, *q, *k, *v, *att;
    cudaGetSymbolAddress((void**)&qkv, g_qkv);
    cudaGetSymbolAddress((void**)&q,   g_q);
    cudaGetSymbolAddress((void**)&k,   g_k);
    cudaGetSymbolAddress((void**)&v,   g_v);
    cudaGetSymbolAddress((void**)&att, g_att);

    const int attn_smem = 4 * 64 * SPITCH * 4;
    cudaFuncSetAttribute(attn_kernel,
                         cudaFuncAttributeMaxDynamicSharedMemorySize, attn_smem);

    // 1) qkv = x @ qkv_w^T    [4096, 2304]
    sgemm_nt<false><<<dim3(2304 / 128, MROWS / 128), 256>>>(
        x, qkv_w, nullptr, qkv, MROWS, 3 * DIMC, DIMC);

    // 2) rmsnorm + rope + scale + transpose to [BH, N, DH]
    prep_kernel<<<(MROWS * NH * 32) / 256, 256>>>(
        qkv, positions, qn_w, kn_w, q, k, v);

    // 3) attention
    attn_kernel<<<dim3(NSEQ / 64, BHN), 256, attn_smem>>>(q, k, v, att);

    // 4) out = att @ proj_w^T + proj_b
    sgemm_nt<true><<<dim3(DIMC / 128, MROWS / 128), 256>>>(
        att, proj_w, proj_b, out, MROWS, DIMC, DIMC);
}

// round 3
// speedup vs baseline: 3.8215x; 3.8215x over previous
#include <cuda_runtime.h>
#include <math.h>
#include <stdint.h>

#define BB 2
#define NSEQ 2048
#define DIMC 768
#define NH 12
#define DH 64
#define BHN (BB*NH)
#define MROWS (BB*NSEQ)
// 0.125 * log2(e): softmax done in base-2
#define QSCALE_L2E 0.18033688011112042f

// ---------------- scratch (static device globals; no allocation) -------------
__device__ float g_qkv[(size_t)MROWS * 3 * DIMC];
__device__ float g_q[(size_t)BHN * NSEQ * DH];
__device__ float g_k[(size_t)BHN * NSEQ * DH];
__device__ float g_v[(size_t)BHN * NSEQ * DH];
__device__ float g_att[(size_t)MROWS * DIMC];

// ---------------- helpers ---------------------------------------------------
// tf32 round: result is the tf32 bit pattern in a b32 register.
__device__ __forceinline__ uint32_t tf32b(float x) {
    uint32_t r; asm("cvt.rna.tf32.f32 %0, %1;" : "=r"(r) : "f"(x)); return r;
}
__device__ __forceinline__ float tf32f(float x) {
    return __uint_as_float(tf32b(x));
}
__device__ __forceinline__ uint32_t fbits(float x) { return __float_as_uint(x); }

__device__ __forceinline__ void mma_tf32(float4& d,
    uint32_t a0, uint32_t a1, uint32_t a2, uint32_t a3,
    uint32_t b0, uint32_t b1)
{
    asm volatile(
        "mma.sync.aligned.m16n8k8.row.col.f32.tf32.tf32.f32 "
        "{%0,%1,%2,%3}, {%4,%5,%6,%7}, {%8,%9}, {%0,%1,%2,%3};"
        : "+f"(d.x), "+f"(d.y), "+f"(d.z), "+f"(d.w)
        : "r"(a0), "r"(a1), "r"(a2), "r"(a3), "r"(b0), "r"(b1));
}

// exp2 via FMA polynomial + exponent splice — avoids the MUFU pipe entirely.
// Valid for t <= 0 (softmax domain); clamps at -120 (underflow to ~0).
__device__ __forceinline__ float exp2_fast(float t) {
    t = fmaxf(t, -120.0f);
    float z = t + 12582912.0f;                 // 1.5*2^23: round-to-int trick
    int  i = __float_as_int(z) - 0x4B400000;
    float f = t - (z - 12582912.0f);           // f in [-0.5, 0.5]
    float p = 1.3333558e-3f;                   // Taylor of 2^f
    p = fmaf(p, f, 9.6181291e-3f);
    p = fmaf(p, f, 5.5504109e-2f);
    p = fmaf(p, f, 2.4022651e-1f);
    p = fmaf(p, f, 6.9314718e-1f);
    p = fmaf(p, f, 1.0f);
    return __int_as_float((i + 127) << 23) * p;
}

// ---------------- tf32 GEMM: C[m][n] = sum_k A[m][k] * W[n][k] (+bias) ------
// 128x128 tile, BK=32, 256 threads (8 warps, 2m x 4n), warp tile 64x32.
template<bool BIAS>
__global__ void __launch_bounds__(256) gemm_tf32(
    const float* __restrict__ A, const float* __restrict__ W,
    const float* __restrict__ bias, float* __restrict__ C,
    int M, int N, int K)
{
    __shared__ float As[128 * 36];
    __shared__ float Ws[128 * 36];

    const int tid = threadIdx.x;
    const int lane = tid & 31, wid = tid >> 5;
    const int g = lane >> 2, tg = lane & 3;
    const int wm = (wid & 1) * 64;
    const int wn = (wid >> 1) * 32;
    const int mtile = blockIdx.y * 128, ntile = blockIdx.x * 128;

    const int lr = tid >> 3;     // 0..31
    const int lc4 = tid & 7;     // float4 col 0..7

    const float* Ap = A + (size_t)mtile * K;
    const float* Wp = W + (size_t)ntile * K;

    float4 rA[4], rW[4];
#pragma unroll
    for (int i = 0; i < 4; i++) {
        rA[i] = *(const float4*)(Ap + (size_t)(lr + i * 32) * K + lc4 * 4);
        rW[i] = *(const float4*)(Wp + (size_t)(lr + i * 32) * K + lc4 * 4);
    }

    float4 acc[4][4];
#pragma unroll
    for (int mt = 0; mt < 4; mt++)
#pragma unroll
        for (int nt = 0; nt < 4; nt++) acc[mt][nt] = make_float4(0.f, 0.f, 0.f, 0.f);

    for (int k0 = 0; k0 < K; k0 += 32) {
        __syncthreads();
#pragma unroll
        for (int i = 0; i < 4; i++) {
            float* as = &As[(lr + i * 32) * 36 + lc4 * 4];
            as[0] = tf32f(rA[i].x); as[1] = tf32f(rA[i].y);
            as[2] = tf32f(rA[i].z); as[3] = tf32f(rA[i].w);
            float* ws = &Ws[(lr + i * 32) * 36 + lc4 * 4];
            ws[0] = tf32f(rW[i].x); ws[1] = tf32f(rW[i].y);
            ws[2] = tf32f(rW[i].z); ws[3] = tf32f(rW[i].w);
        }
        __syncthreads();
        if (k0 + 32 < K) {
#pragma unroll
            for (int i = 0; i < 4; i++) {
                rA[i] = *(const float4*)(Ap + (size_t)(lr + i * 32) * K + k0 + 32 + lc4 * 4);
                rW[i] = *(const float4*)(Wp + (size_t)(lr + i * 32) * K + k0 + 32 + lc4 * 4);
            }
        }
#pragma unroll
        for (int ks = 0; ks < 4; ks++) {
            const int c = ks * 8 + tg;
            uint32_t af[4][4], bf[4][2];
#pragma unroll
            for (int mt = 0; mt < 4; mt++) {
                int r0 = wm + mt * 16 + g;
                af[mt][0] = fbits(As[r0 * 36 + c]);
                af[mt][1] = fbits(As[(r0 + 8) * 36 + c]);
                af[mt][2] = fbits(As[r0 * 36 + c + 4]);
                af[mt][3] = fbits(As[(r0 + 8) * 36 + c + 4]);
            }
#pragma unroll
            for (int nt = 0; nt < 4; nt++) {
                int n0 = wn + nt * 8 + g;
                bf[nt][0] = fbits(Ws[n0 * 36 + c]);
                bf[nt][1] = fbits(Ws[n0 * 36 + c + 4]);
            }
#pragma unroll
            for (int mt = 0; mt < 4; mt++)
#pragma unroll
                for (int nt = 0; nt < 4; nt++)
                    mma_tf32(acc[mt][nt], af[mt][0], af[mt][1], af[mt][2], af[mt][3],
                             bf[nt][0], bf[nt][1]);
        }
    }

#pragma unroll
    for (int mt = 0; mt < 4; mt++) {
        int r0 = mtile + wm + mt * 16 + g;
#pragma unroll
        for (int nt = 0; nt < 4; nt++) {
            int col = ntile + wn + nt * 8 + 2 * tg;
            float4 v = acc[mt][nt];
            float b0v = 0.f, b1v = 0.f;
            if (BIAS) { b0v = bias[col]; b1v = bias[col + 1]; }
            float2 t0 = {v.x + b0v, v.y + b1v};
            float2 t1 = {v.z + b0v, v.w + b1v};
            *(float2*)(C + (size_t)r0 * N + col) = t0;
            *(float2*)(C + (size_t)(r0 + 8) * N + col) = t1;
        }
    }
}

// -------- fused rmsnorm + 3D RoPE + q-scale(log2e) + tf32 round + transpose -
__global__ void __launch_bounds__(256) prep_kernel(
    const float* __restrict__ qkv, const float* __restrict__ positions,
    const float* __restrict__ qn_w, const float* __restrict__ kn_w,
    float* __restrict__ qT, float* __restrict__ kT, float* __restrict__ vT)
{
    int gwarp = (blockIdx.x * blockDim.x + threadIdx.x) >> 5;
    int lane  = threadIdx.x & 31;
    if (gwarp >= MROWS * NH) return;
    int h = gwarp % NH;
    int m = gwarp / NH;
    int b = m / NSEQ;
    int t = m % NSEQ;

    const float* row = qkv + (size_t)m * (3 * DIMC) + h * DH;
    float2 q = *(const float2*)(row + 2 * lane);
    float2 k = *(const float2*)(row + DIMC + 2 * lane);
    float2 v = *(const float2*)(row + 2 * DIMC + 2 * lane);

    float sq = q.x * q.x + q.y * q.y;
    float sk = k.x * k.x + k.y * k.y;
#pragma unroll
    for (int off = 16; off; off >>= 1) {
        sq += __shfl_xor_sync(0xffffffffu, sq, off);
        sk += __shfl_xor_sync(0xffffffffu, sk, off);
    }
    float rq = rsqrtf(sq * (1.0f / 64.0f) + 1e-6f);
    float rk = rsqrtf(sk * (1.0f / 64.0f) + 1e-6f);
    float2 wq = *(const float2*)(qn_w + 2 * lane);
    float2 wk = *(const float2*)(kn_w + 2 * lane);
    q.x *= rq * wq.x; q.y *= rq * wq.y;
    k.x *= rk * wk.x; k.y *= rk * wk.y;

    if (lane < 30) {                   // rope pairs: first 60 dims
        int p = lane / 10;
        int f = lane % 10;
        float pos  = positions[(size_t)m * 3 + p];
        float freq = __expf(-0.92103403719761836f * (float)f);  // 10000^(-f/10)
        float ang  = pos * freq;
        float s, c;
        __sincosf(ang, &s, &c);
        float qe = q.x * c - q.y * s, qo = q.x * s + q.y * c;
        float ke = k.x * c - k.y * s, ko = k.x * s + k.y * c;
        q.x = qe; q.y = qo; k.x = ke; k.y = ko;
    }
    q.x *= QSCALE_L2E; q.y *= QSCALE_L2E;

    // round everything to tf32 once, here
    q.x = tf32f(q.x); q.y = tf32f(q.y);
    k.x = tf32f(k.x); k.y = tf32f(k.y);
    v.x = tf32f(v.x); v.y = tf32f(v.y);

    size_t o = ((size_t)(b * NH + h) * NSEQ + t) * DH + 2 * lane;
    *(float2*)(qT + o) = q;
    *(float2*)(kT + o) = k;
    *(float2*)(vT + o) = v;
}

// ---------------- flash-attention on tensor cores (tf32, base-2 softmax) ----
// 128 threads (4 warps); each warp owns 16 query rows. Br=64, Bc=64, DH=64.
#define AP 68
__global__ void __launch_bounds__(128, 3) attn_tc(
    const float* __restrict__ qT, const float* __restrict__ kT,
    const float* __restrict__ vT, float* __restrict__ out)
{
    extern __shared__ float sm[];
    float* Qs = sm;               // 64 x AP   (aliased by Ps after preload)
    float* Ks = sm + 64 * AP;     // 64 x AP   [key][d]
    float* Vs = sm + 2 * 64 * AP; // 64 x AP   [key][d]
    float* Ps = Qs;               // warp-private rows -> safe alias

    const int tid = threadIdx.x, lane = tid & 31, w = tid >> 5;
    const int g = lane >> 2, tg = lane & 3;
    const int qt = blockIdx.x, bh = blockIdx.y;

    const float* qb = qT + ((size_t)bh * NSEQ + qt * 64) * DH;
#pragma unroll
    for (int i = 0; i < 8; i++) {
        int idx = tid + i * 128, r = idx >> 4, c4 = idx & 15;
        *(float4*)&Qs[r * AP + c4 * 4] = *(const float4*)(qb + r * 64 + c4 * 4);
    }
    __syncthreads();

    // hoist Q fragments into registers (reused for all 32 KV chunks)
    uint32_t qa[8][4];
#pragma unroll
    for (int kt = 0; kt < 8; kt++) {
        int c = kt * 8 + tg;
        int r0 = w * 16 + g;
        qa[kt][0] = fbits(Qs[r0 * AP + c]);
        qa[kt][1] = fbits(Qs[(r0 + 8) * AP + c]);
        qa[kt][2] = fbits(Qs[r0 * AP + c + 4]);
        qa[kt][3] = fbits(Qs[(r0 + 8) * AP + c + 4]);
    }

    float4 accO[8];
#pragma unroll
    for (int nt = 0; nt < 8; nt++) accO[nt] = make_float4(0.f, 0.f, 0.f, 0.f);
    float m0 = -1e30f, m1 = -1e30f, l0 = 0.f, l1 = 0.f;

    const int pr0 = (w * 16 + g) * AP;
    const int pr1 = (w * 16 + g + 8) * AP;

    for (int kc = 0; kc < 32; kc++) {
        const float* kb = kT + ((size_t)bh * NSEQ + kc * 64) * DH;
        const float* vb = vT + ((size_t)bh * NSEQ + kc * 64) * DH;
        __syncthreads();   // prior chunk's PV mma done before Ks/Vs overwrite
#pragma unroll
        for (int i = 0; i < 8; i++) {
            int idx = tid + i * 128, r = idx >> 4, c4 = idx & 15;
            *(float4*)&Ks[r * AP + c4 * 4] = *(const float4*)(kb + r * 64 + c4 * 4);
            *(float4*)&Vs[r * AP + c4 * 4] = *(const float4*)(vb + r * 64 + c4 * 4);
        }
        __syncthreads();

        // S = Q @ K^T (scores already in base-2 logits)
        float4 s[8];
#pragma unroll
        for (int nt = 0; nt < 8; nt++) s[nt] = make_float4(0.f, 0.f, 0.f, 0.f);
#pragma unroll
        for (int kt = 0; kt < 8; kt++) {
            const int c = kt * 8 + tg;
            uint32_t kb0[8], kb1[8];
#pragma unroll
            for (int nt = 0; nt < 8; nt++) {
                int n0 = nt * 8 + g;
                kb0[nt] = fbits(Ks[n0 * AP + c]);
                kb1[nt] = fbits(Ks[n0 * AP + c + 4]);
            }
#pragma unroll
            for (int nt = 0; nt < 8; nt++)
                mma_tf32(s[nt], qa[kt][0], qa[kt][1], qa[kt][2], qa[kt][3],
                         kb0[nt], kb1[nt]);
        }

        // online softmax (rows g and g+8 of this warp's 16-row slice)
        float rm0 = -1e30f, rm1 = -1e30f;
#pragma unroll
        for (int nt = 0; nt < 8; nt++) {
            rm0 = fmaxf(rm0, fmaxf(s[nt].x, s[nt].y));
            rm1 = fmaxf(rm1, fmaxf(s[nt].z, s[nt].w));
        }
        rm0 = fmaxf(rm0, __shfl_xor_sync(0xffffffffu, rm0, 1));
        rm0 = fmaxf(rm0, __shfl_xor_sync(0xffffffffu, rm0, 2));
        rm1 = fmaxf(rm1, __shfl_xor_sync(0xffffffffu, rm1, 1));
        rm1 = fmaxf(rm1, __shfl_xor_sync(0xffffffffu, rm1, 2));
        float nm0 = fmaxf(m0, rm0), nm1 = fmaxf(m1, rm1);
        float cr0 = exp2_fast(m0 - nm0), cr1 = exp2_fast(m1 - nm1);
        m0 = nm0; m1 = nm1;

        float sum0 = 0.f, sum1 = 0.f;
#pragma unroll
        for (int nt = 0; nt < 8; nt++) {
            float p00 = exp2_fast(s[nt].x - nm0);
            float p01 = exp2_fast(s[nt].y - nm0);
            float p10 = exp2_fast(s[nt].z - nm1);
            float p11 = exp2_fast(s[nt].w - nm1);
            sum0 += p00 + p01; sum1 += p10 + p11;
            float2 t0 = {tf32f(p00), tf32f(p01)};
            float2 t1 = {tf32f(p10), tf32f(p11)};
            *(float2*)&Ps[pr0 + nt * 8 + 2 * tg] = t0;
            *(float2*)&Ps[pr1 + nt * 8 + 2 * tg] = t1;
        }
        sum0 += __shfl_xor_sync(0xffffffffu, sum0, 1);
        sum0 += __shfl_xor_sync(0xffffffffu, sum0, 2);
        sum1 += __shfl_xor_sync(0xffffffffu, sum1, 1);
        sum1 += __shfl_xor_sync(0xffffffffu, sum1, 2);
        l0 = l0 * cr0 + sum0;
        l1 = l1 * cr1 + sum1;
#pragma unroll
        for (int nt = 0; nt < 8; nt++) {
            accO[nt].x *= cr0; accO[nt].y *= cr0;
            accO[nt].z *= cr1; accO[nt].w *= cr1;
        }
        __syncwarp();   // Ps stores visible to other lanes of this warp

        // O += P @ V
#pragma unroll
        for (int kt = 0; kt < 8; kt++) {
            const int c = kt * 8 + tg;
            uint32_t a0 = fbits(Ps[pr0 + c]);
            uint32_t a1 = fbits(Ps[pr1 + c]);
            uint32_t a2 = fbits(Ps[pr0 + c + 4]);
            uint32_t a3 = fbits(Ps[pr1 + c + 4]);
#pragma unroll
            for (int nt = 0; nt < 8; nt++) {
                int n0 = nt * 8 + g;
                uint32_t vb0 = fbits(Vs[c * AP + n0]);
                uint32_t vb1 = fbits(Vs[(c + 4) * AP + n0]);
                mma_tf32(accO[nt], a0, a1, a2, a3, vb0, vb1);
            }
        }
    }

    // epilogue: out[b*N + q][h*64 + d]
    const int b = bh / NH, h = bh % NH;
    const int r0 = qt * 64 + w * 16 + g;
    const float i0 = 1.f / l0, i1 = 1.f / l1;
#pragma unroll
    for (int nt = 0; nt < 8; nt++) {
        int col = h * 64 + nt * 8 + 2 * tg;
        float2 t0 = {accO[nt].x * i0, accO[nt].y * i0};
        float2 t1 = {accO[nt].z * i1, accO[nt].w * i1};
        *(float2*)(out + (size_t)(b * NSEQ + r0) * DIMC + col) = t0;
        *(float2*)(out + (size_t)(b * NSEQ + r0 + 8) * DIMC + col) = t1;
    }
}

// ---------------- launch ----------------------------------------------------
extern "C" void kernel_launch(void* const* d_in, const int* in_sizes, int n_in,
                              void* d_out, int out_size)
{
    (void)in_sizes; (void)n_in; (void)out_size;
    const float* x         = (const float*)d_in[0];
    const float* positions = (const float*)d_in[1];
    const float* qkv_w     = (const float*)d_in[2];
    const float* proj_w    = (const float*)d_in[3];
    const float* proj_b    = (const float*)d_in[4];
    const float* qn_w      = (const float*)d_in[5];
    const float* kn_w      = (const float*)d_in[6];
    float* out = (float*)d_out;

    float *qkv, *q, *k, *v, *att;
    cudaGetSymbolAddress((void**)&qkv, g_qkv);
    cudaGetSymbolAddress((void**)&q,   g_q);
    cudaGetSymbolAddress((void**)&k,   g_k);
    cudaGetSymbolAddress((void**)&v,   g_v);
    cudaGetSymbolAddress((void**)&att, g_att);

    const int attn_smem = 3 * 64 * AP * 4;   // 52224 B
    cudaFuncSetAttribute(attn_tc,
                         cudaFuncAttributeMaxDynamicSharedMemorySize, attn_smem);

    // 1) qkv = x @ qkv_w^T    [4096, 2304]
    gemm_tf32<false><<<dim3(2304 / 128, MROWS / 128), 256>>>(
        x, qkv_w, nullptr, qkv, MROWS, 3 * DIMC, DIMC);

    // 2) rmsnorm + rope + scale + tf32 round + transpose to [BH, N, DH]
    prep_kernel<<<(MROWS * NH * 32) / 256, 256>>>(
        qkv, positions, qn_w, kn_w, q, k, v);

    // 3) attention (tensor-core flash attention, base-2 softmax)
    attn_tc<<<dim3(NSEQ / 64, BHN), 128, attn_smem>>>(q, k, v, att);

    // 4) out = att @ proj_w^T + proj_b
    gemm_tf32<true><<<dim3(DIMC / 128, MROWS / 128), 256>>>(
        att, proj_w, proj_b, out, MROWS, DIMC, DIMC);
}

// round 4
// speedup vs baseline: 7.3396x; 1.9206x over previous
#include <cuda_runtime.h>
#include <cuda_fp16.h>
#include <math.h>
#include <stdint.h>

#define BB 2
#define NSEQ 2048
#define DIMC 768
#define NH 12
#define DH 64
#define BHN (BB*NH)
#define MROWS (BB*NSEQ)
// 0.125 * log2(e): softmax done in base-2
#define QSCALE_L2E 0.18033688011112042f

// ---------------- scratch (static device globals; no allocation) -------------
__device__ float  g_qkv[(size_t)MROWS * 3 * DIMC];          // fp32 qkv
__device__ float  g_att[(size_t)MROWS * DIMC];              // fp32 attention out
__device__ __half g_xh[(size_t)MROWS * DIMC];
__device__ __half g_qkvwh[(size_t)3 * DIMC * DIMC];
__device__ __half g_projwh[(size_t)DIMC * DIMC];
__device__ __half g_atth[(size_t)MROWS * DIMC];
__device__ __half g_q[(size_t)BHN * NSEQ * DH];
__device__ __half g_k[(size_t)BHN * NSEQ * DH];
__device__ __half g_v[(size_t)BHN * NSEQ * DH];

// ---------------- helpers ---------------------------------------------------
__device__ __forceinline__ uint32_t h2u(float a, float b) {
    __half2 h = __floats2half2_rn(a, b);
    return *reinterpret_cast<uint32_t*>(&h);
}
__device__ __forceinline__ uint32_t smaddr(const void* p) {
    return (uint32_t)__cvta_generic_to_shared(p);
}
__device__ __forceinline__ void cp16(void* dst, const void* src) {
    asm volatile("cp.async.cg.shared.global [%0], [%1], 16;"
                 :: "r"(smaddr(dst)), "l"(src));
}
#define CP_COMMIT() asm volatile("cp.async.commit_group;")
#define CP_WAIT(n)  asm volatile("cp.async.wait_group %0;" :: "n"(n))

__device__ __forceinline__ void ldsm4(uint32_t& r0, uint32_t& r1,
                                      uint32_t& r2, uint32_t& r3, const void* p) {
    asm volatile("ldmatrix.sync.aligned.m8n8.x4.shared.b16 {%0,%1,%2,%3}, [%4];"
                 : "=r"(r0), "=r"(r1), "=r"(r2), "=r"(r3) : "r"(smaddr(p)));
}
__device__ __forceinline__ void ldsm4t(uint32_t& r0, uint32_t& r1,
                                       uint32_t& r2, uint32_t& r3, const void* p) {
    asm volatile("ldmatrix.sync.aligned.m8n8.x4.trans.shared.b16 {%0,%1,%2,%3}, [%4];"
                 : "=r"(r0), "=r"(r1), "=r"(r2), "=r"(r3) : "r"(smaddr(p)));
}
__device__ __forceinline__ void mma_h(float4& d,
    uint32_t a0, uint32_t a1, uint32_t a2, uint32_t a3,
    uint32_t b0, uint32_t b1)
{
    asm volatile(
        "mma.sync.aligned.m16n8k16.row.col.f32.f16.f16.f32 "
        "{%0,%1,%2,%3}, {%4,%5,%6,%7}, {%8,%9}, {%0,%1,%2,%3};"
        : "+f"(d.x), "+f"(d.y), "+f"(d.z), "+f"(d.w)
        : "r"(a0), "r"(a1), "r"(a2), "r"(a3), "r"(b0), "r"(b1));
}

// exp2 via FMA polynomial + exponent splice — no MUFU in the hot loop.
__device__ __forceinline__ float exp2_fast(float t) {
    t = fmaxf(t, -120.0f);
    float z = t + 12582912.0f;
    int  i = __float_as_int(z) - 0x4B400000;
    float f = t - (z - 12582912.0f);
    float p = 1.3333558e-3f;
    p = fmaf(p, f, 9.6181291e-3f);
    p = fmaf(p, f, 5.5504109e-2f);
    p = fmaf(p, f, 2.4022651e-1f);
    p = fmaf(p, f, 6.9314718e-1f);
    p = fmaf(p, f, 1.0f);
    return __int_as_float((i + 127) << 23) * p;
}

// ---------------- fp32 -> fp16 convert --------------------------------------
__global__ void __launch_bounds__(256) f2h_kernel(const float* __restrict__ in,
                                                  __half* __restrict__ out, int n4)
{
    int i = blockIdx.x * blockDim.x + threadIdx.x;
    if (i >= n4) return;
    float4 v = *(const float4*)(in + (size_t)i * 4);
    uint2 o;
    o.x = h2u(v.x, v.y);
    o.y = h2u(v.z, v.w);
    *(uint2*)(out + (size_t)i * 4) = o;
}

// ---------------- fp16 GEMM: C[m][n] = sum_k A[m][k] * W[n][k] (+bias) ------
// 128x128 tile, BK=32, 256 threads (8 warps, 2m x 4n), warp tile 64x32.
// cp.async double-buffered smem (pitch 40 halves), ldmatrix fragments.
#define GP 40
template<bool BIAS>
__global__ void __launch_bounds__(256) gemm_h(
    const __half* __restrict__ A, const __half* __restrict__ W,
    const float* __restrict__ bias, float* __restrict__ C,
    int M, int N, int K)
{
    __shared__ __half As[2][128 * GP];
    __shared__ __half Ws[2][128 * GP];

    const int tid = threadIdx.x;
    const int lane = tid & 31, wid = tid >> 5;
    const int g = lane >> 2, tg = lane & 3;
    const int wm = (wid & 1) * 64;
    const int wn = (wid >> 1) * 32;
    const int mtile = blockIdx.y * 128, ntile = blockIdx.x * 128;

    const int ldr = tid >> 2;            // 0..63  (x2 passes -> 128 rows)
    const int ldc = (tid & 3) * 8;       // 0,8,16,24

    auto issue = [&](int k0, int st) {
#pragma unroll
        for (int i = 0; i < 2; i++) {
            int r = ldr + i * 64;
            cp16(&As[st][r * GP + ldc], A + (size_t)(mtile + r) * K + k0 + ldc);
            cp16(&Ws[st][r * GP + ldc], W + (size_t)(ntile + r) * K + k0 + ldc);
        }
        CP_COMMIT();
    };

    issue(0, 0);
    issue(32, 1);

    float4 acc[4][4];
#pragma unroll
    for (int mt = 0; mt < 4; mt++)
#pragma unroll
        for (int nt = 0; nt < 4; nt++) acc[mt][nt] = make_float4(0.f, 0.f, 0.f, 0.f);

    const int NIT = K / 32;
    const int arow = (lane & 15);
    const int acol = ((lane >> 4) & 1) * 8;
    const int brow = ((lane & 16) >> 1) + (lane & 7);
    const int bcol = (lane & 8);

    for (int it = 0; it < NIT; it++) {
        if (it == NIT - 1) { CP_WAIT(0); } else { CP_WAIT(1); }
        __syncthreads();
        const int st = it & 1;
#pragma unroll
        for (int ks = 0; ks < 2; ks++) {
            uint32_t af[4][4], bf[4][2];
#pragma unroll
            for (int mt = 0; mt < 4; mt++)
                ldsm4(af[mt][0], af[mt][1], af[mt][2], af[mt][3],
                      &As[st][(wm + mt * 16 + arow) * GP + ks * 16 + acol]);
#pragma unroll
            for (int p = 0; p < 2; p++)
                ldsm4(bf[2 * p][0], bf[2 * p][1], bf[2 * p + 1][0], bf[2 * p + 1][1],
                      &Ws[st][(wn + p * 16 + brow) * GP + ks * 16 + bcol]);
#pragma unroll
            for (int mt = 0; mt < 4; mt++)
#pragma unroll
                for (int nt = 0; nt < 4; nt++)
                    mma_h(acc[mt][nt], af[mt][0], af[mt][1], af[mt][2], af[mt][3],
                          bf[nt][0], bf[nt][1]);
        }
        __syncthreads();
        if (it + 2 < NIT) issue((it + 2) * 32, st);
    }

#pragma unroll
    for (int mt = 0; mt < 4; mt++) {
        int r0 = mtile + wm + mt * 16 + g;
#pragma unroll
        for (int nt = 0; nt < 4; nt++) {
            int col = ntile + wn + nt * 8 + 2 * tg;
            float4 v = acc[mt][nt];
            float b0v = 0.f, b1v = 0.f;
            if (BIAS) { b0v = bias[col]; b1v = bias[col + 1]; }
            float2 t0 = {v.x + b0v, v.y + b1v};
            float2 t1 = {v.z + b0v, v.w + b1v};
            *(float2*)(C + (size_t)r0 * N + col) = t0;
            *(float2*)(C + (size_t)(r0 + 8) * N + col) = t1;
        }
    }
}

// -------- fused rmsnorm + 3D RoPE + q-scale(log2e) + fp16 + transpose -------
__global__ void __launch_bounds__(256) prep_kernel(
    const float* __restrict__ qkv, const float* __restrict__ positions,
    const float* __restrict__ qn_w, const float* __restrict__ kn_w,
    __half* __restrict__ qT, __half* __restrict__ kT, __half* __restrict__ vT)
{
    int gwarp = (blockIdx.x * blockDim.x + threadIdx.x) >> 5;
    int lane  = threadIdx.x & 31;
    if (gwarp >= MROWS * NH) return;
    int h = gwarp % NH;
    int m = gwarp / NH;
    int b = m / NSEQ;
    int t = m % NSEQ;

    const float* row = qkv + (size_t)m * (3 * DIMC) + h * DH;
    float2 q = *(const float2*)(row + 2 * lane);
    float2 k = *(const float2*)(row + DIMC + 2 * lane);
    float2 v = *(const float2*)(row + 2 * DIMC + 2 * lane);

    float sq = q.x * q.x + q.y * q.y;
    float sk = k.x * k.x + k.y * k.y;
#pragma unroll
    for (int off = 16; off; off >>= 1) {
        sq += __shfl_xor_sync(0xffffffffu, sq, off);
        sk += __shfl_xor_sync(0xffffffffu, sk, off);
    }
    float rq = rsqrtf(sq * (1.0f / 64.0f) + 1e-6f);
    float rk = rsqrtf(sk * (1.0f / 64.0f) + 1e-6f);
    float2 wq = *(const float2*)(qn_w + 2 * lane);
    float2 wk = *(const float2*)(kn_w + 2 * lane);
    q.x *= rq * wq.x; q.y *= rq * wq.y;
    k.x *= rk * wk.x; k.y *= rk * wk.y;

    if (lane < 30) {                   // rope pairs: first 60 dims
        int p = lane / 10;
        int f = lane % 10;
        float pos  = positions[(size_t)m * 3 + p];
        float freq = __expf(-0.92103403719761836f * (float)f);  // 10000^(-f/10)
        float ang  = pos * freq;
        float s, c;
        __sincosf(ang, &s, &c);
        float qe = q.x * c - q.y * s, qo = q.x * s + q.y * c;
        float ke = k.x * c - k.y * s, ko = k.x * s + k.y * c;
        q.x = qe; q.y = qo; k.x = ke; k.y = ko;
    }
    q.x *= QSCALE_L2E; q.y *= QSCALE_L2E;

    size_t o = ((size_t)(b * NH + h) * NSEQ + t) * DH + 2 * lane;
    *(uint32_t*)(qT + o) = h2u(q.x, q.y);
    *(uint32_t*)(kT + o) = h2u(k.x, k.y);
    *(uint32_t*)(vT + o) = h2u(v.x, v.y);
}

// ---------------- fp16 flash-attention (base-2 softmax, register P) ---------
// 128 threads (4 warps); warp owns 16 query rows. Br=64, Bc=64, DH=64.
#define AP 72
__global__ void __launch_bounds__(128) attn_h(
    const __half* __restrict__ qT, const __half* __restrict__ kT,
    const __half* __restrict__ vT, float* __restrict__ out)
{
    __shared__ __half Qs[64 * AP];
    __shared__ __half Ks[2][64 * AP];
    __shared__ __half Vs[2][64 * AP];

    const int tid = threadIdx.x, lane = tid & 31, w = tid >> 5;
    const int g = lane >> 2, tg = lane & 3;
    const int qt = blockIdx.x, bh = blockIdx.y;

    const int ldr = tid >> 1;           // 0..63
    const int ldc = (tid & 1) * 8;      // two passes cover 0..31? no: see below

    auto issue_kv = [&](int kc, int st) {
        const __half* kb = kT + ((size_t)bh * NSEQ + kc * 64) * DH;
        const __half* vb = vT + ((size_t)bh * NSEQ + kc * 64) * DH;
#pragma unroll
        for (int i = 0; i < 4; i++) {
            int idx = tid + i * 128;
            int r = idx >> 3, c = (idx & 7) * 8;
            cp16(&Ks[st][r * AP + c], kb + r * 64 + c);
            cp16(&Vs[st][r * AP + c], vb + r * 64 + c);
        }
        CP_COMMIT();
    };
    (void)ldr; (void)ldc;

    // Q tile (direct load)
    const __half* qb = qT + ((size_t)bh * NSEQ + qt * 64) * DH;
#pragma unroll
    for (int i = 0; i < 4; i++) {
        int idx = tid + i * 128;
        int r = idx >> 3, c = (idx & 7) * 8;
        *(uint4*)&Qs[r * AP + c] = *(const uint4*)(qb + r * 64 + c);
    }

    issue_kv(0, 0);
    issue_kv(1, 1);
    __syncthreads();

    // hoist Q fragments
    const int arow = (lane & 15);
    const int acol = ((lane >> 4) & 1) * 8;
    const int brow = ((lane & 16) >> 1) + (lane & 7);
    const int bcol = (lane & 8);

    uint32_t qa[4][4];
#pragma unroll
    for (int kt = 0; kt < 4; kt++)
        ldsm4(qa[kt][0], qa[kt][1], qa[kt][2], qa[kt][3],
              &Qs[(w * 16 + arow) * AP + kt * 16 + acol]);

    float4 accO[8];
#pragma unroll
    for (int nt = 0; nt < 8; nt++) accO[nt] = make_float4(0.f, 0.f, 0.f, 0.f);
    float m0 = -1e30f, m1 = -1e30f, l0 = 0.f, l1 = 0.f;

    for (int kc = 0; kc < 32; kc++) {
        if (kc == 31) { CP_WAIT(0); } else { CP_WAIT(1); }
        __syncthreads();
        const int st = kc & 1;

        // ---- S = Q @ K^T ----
        float4 s[8];
#pragma unroll
        for (int nt = 0; nt < 8; nt++) s[nt] = make_float4(0.f, 0.f, 0.f, 0.f);
#pragma unroll
        for (int kt = 0; kt < 4; kt++) {
            uint32_t kb[8][2];
#pragma unroll
            for (int p = 0; p < 4; p++)
                ldsm4(kb[2 * p][0], kb[2 * p][1], kb[2 * p + 1][0], kb[2 * p + 1][1],
                      &Ks[st][(p * 16 + brow) * AP + kt * 16 + bcol]);
#pragma unroll
            for (int nt = 0; nt < 8; nt++)
                mma_h(s[nt], qa[kt][0], qa[kt][1], qa[kt][2], qa[kt][3],
                      kb[nt][0], kb[nt][1]);
        }

        // ---- online softmax (rows g and g+8) ----
        float rm0 = -1e30f, rm1 = -1e30f;
#pragma unroll
        for (int nt = 0; nt < 8; nt++) {
            rm0 = fmaxf(rm0, fmaxf(s[nt].x, s[nt].y));
            rm1 = fmaxf(rm1, fmaxf(s[nt].z, s[nt].w));
        }
        rm0 = fmaxf(rm0, __shfl_xor_sync(0xffffffffu, rm0, 1));
        rm0 = fmaxf(rm0, __shfl_xor_sync(0xffffffffu, rm0, 2));
        rm1 = fmaxf(rm1, __shfl_xor_sync(0xffffffffu, rm1, 1));
        rm1 = fmaxf(rm1, __shfl_xor_sync(0xffffffffu, rm1, 2));
        float nm0 = fmaxf(m0, rm0), nm1 = fmaxf(m1, rm1);
        float cr0 = exp2_fast(m0 - nm0), cr1 = exp2_fast(m1 - nm1);
        m0 = nm0; m1 = nm1;

        float sum0 = 0.f, sum1 = 0.f;
#pragma unroll
        for (int nt = 0; nt < 8; nt++) {
            s[nt].x = exp2_fast(s[nt].x - nm0);
            s[nt].y = exp2_fast(s[nt].y - nm0);
            s[nt].z = exp2_fast(s[nt].z - nm1);
            s[nt].w = exp2_fast(s[nt].w - nm1);
            sum0 += s[nt].x + s[nt].y;
            sum1 += s[nt].z + s[nt].w;
        }
        sum0 += __shfl_xor_sync(0xffffffffu, sum0, 1);
        sum0 += __shfl_xor_sync(0xffffffffu, sum0, 2);
        sum1 += __shfl_xor_sync(0xffffffffu, sum1, 1);
        sum1 += __shfl_xor_sync(0xffffffffu, sum1, 2);
        l0 = l0 * cr0 + sum0;
        l1 = l1 * cr1 + sum1;
#pragma unroll
        for (int nt = 0; nt < 8; nt++) {
            accO[nt].x *= cr0; accO[nt].y *= cr0;
            accO[nt].z *= cr1; accO[nt].w *= cr1;
        }

        // ---- P fragments directly in registers (C-frag layout == A-frag) ----
        uint32_t pa[4][4];
#pragma unroll
        for (int j = 0; j < 4; j++) {
            pa[j][0] = h2u(s[2 * j].x,     s[2 * j].y);
            pa[j][1] = h2u(s[2 * j].z,     s[2 * j].w);
            pa[j][2] = h2u(s[2 * j + 1].x, s[2 * j + 1].y);
            pa[j][3] = h2u(s[2 * j + 1].z, s[2 * j + 1].w);
        }

        // ---- O += P @ V ----
#pragma unroll
        for (int kt = 0; kt < 4; kt++) {
            uint32_t vb[8][2];
#pragma unroll
            for (int q4 = 0; q4 < 4; q4++)
                ldsm4t(vb[2 * q4][0], vb[2 * q4][1], vb[2 * q4 + 1][0], vb[2 * q4 + 1][1],
                       &Vs[st][(kt * 16 + arow) * AP + q4 * 16 + acol]);
#pragma unroll
            for (int nt = 0; nt < 8; nt++)
                mma_h(accO[nt], pa[kt][0], pa[kt][1], pa[kt][2], pa[kt][3],
                      vb[nt][0], vb[nt][1]);
        }
        __syncthreads();
        if (kc + 2 < 32) issue_kv(kc + 2, st);
    }

    // epilogue: out[b*N + q][h*64 + d]
    const int b = bh / NH, h = bh % NH;
    const int r0 = qt * 64 + w * 16 + g;
    const float i0 = 1.f / l0, i1 = 1.f / l1;
#pragma unroll
    for (int nt = 0; nt < 8; nt++) {
        int col = h * 64 + nt * 8 + 2 * tg;
        float2 t0 = {accO[nt].x * i0, accO[nt].y * i0};
        float2 t1 = {accO[nt].z * i1, accO[nt].w * i1};
        *(float2*)(out + (size_t)(b * NSEQ + r0) * DIMC + col) = t0;
        *(float2*)(out + (size_t)(b * NSEQ + r0 + 8) * DIMC + col) = t1;
    }
}

// ---------------- launch ----------------------------------------------------
extern "C" void kernel_launch(void* const* d_in, const int* in_sizes, int n_in,
                              void* d_out, int out_size)
{
    (void)in_sizes; (void)n_in; (void)out_size;
    const float* x         = (const float*)d_in[0];
    const float* positions = (const float*)d_in[1];
    const float* qkv_w     = (const float*)d_in[2];
    const float* proj_w    = (const float*)d_in[3];
    const float* proj_b    = (const float*)d_in[4];
    const float* qn_w      = (const float*)d_in[5];
    const float* kn_w      = (const float*)d_in[6];
    float* out = (float*)d_out;

    float *qkv, *att;
    __half *xh, *qkvwh, *projwh, *atth, *q, *k, *v;
    cudaGetSymbolAddress((void**)&qkv,    g_qkv);
    cudaGetSymbolAddress((void**)&att,    g_att);
    cudaGetSymbolAddress((void**)&xh,     g_xh);
    cudaGetSymbolAddress((void**)&qkvwh,  g_qkvwh);
    cudaGetSymbolAddress((void**)&projwh, g_projwh);
    cudaGetSymbolAddress((void**)&atth,   g_atth);
    cudaGetSymbolAddress((void**)&q,      g_q);
    cudaGetSymbolAddress((void**)&k,      g_k);
    cudaGetSymbolAddress((void**)&v,      g_v);

    // 0) convert inputs to fp16
    {
        int n4;
        n4 = MROWS * DIMC / 4;
        f2h_kernel<<<(n4 + 255) / 256, 256>>>(x, xh, n4);
        n4 = 3 * DIMC * DIMC / 4;
        f2h_kernel<<<(n4 + 255) / 256, 256>>>(qkv_w, qkvwh, n4);
        n4 = DIMC * DIMC / 4;
        f2h_kernel<<<(n4 + 255) / 256, 256>>>(proj_w, projwh, n4);
    }

    // 1) qkv = x @ qkv_w^T    [4096, 2304] (fp32 out)
    gemm_h<false><<<dim3(2304 / 128, MROWS / 128), 256>>>(
        xh, qkvwh, nullptr, qkv, MROWS, 3 * DIMC, DIMC);

    // 2) rmsnorm + rope + scale + fp16 + transpose to [BH, N, DH]
    prep_kernel<<<(MROWS * NH * 32) / 256, 256>>>(
        qkv, positions, qn_w, kn_w, q, k, v);

    // 3) attention (fp16 tensor cores, base-2 softmax, register P)
    attn_h<<<dim3(NSEQ / 64, BHN), 128>>>(q, k, v, att);

    // 4) att -> fp16, then out = att @ proj_w^T + proj_b
    {
        int n4 = MROWS * DIMC / 4;
        f2h_kernel<<<(n4 + 255) / 256, 256>>>(att, atth, n4);
    }
    gemm_h<true><<<dim3(DIMC / 128, MROWS / 128), 256>>>(
        atth, projwh, proj_b, out, MROWS, DIMC, DIMC);
}

// round 5
// speedup vs baseline: 7.4191x; 1.0108x over previous
#include <cuda_runtime.h>
#include <cuda_fp16.h>
#include <math.h>
#include <stdint.h>

#define BB 2
#define NSEQ 2048
#define DIMC 768
#define NH 12
#define DH 64
#define BHN (BB*NH)
#define MROWS (BB*NSEQ)
// 0.125 * log2(e): softmax done in base-2
#define QSCALE_L2E 0.18033688011112042f

// ---------------- scratch (static device globals; no allocation) -------------
__device__ float  g_qkv[(size_t)MROWS * 3 * DIMC];          // fp32 qkv
__device__ __half g_xh[(size_t)MROWS * DIMC];
__device__ __half g_qkvwh[(size_t)3 * DIMC * DIMC];
__device__ __half g_projwh[(size_t)DIMC * DIMC];
__device__ __half g_atth[(size_t)MROWS * DIMC];
__device__ __half g_q[(size_t)BHN * NSEQ * DH];
__device__ __half g_k[(size_t)BHN * NSEQ * DH];
__device__ __half g_v[(size_t)BHN * NSEQ * DH];

// ---------------- helpers ---------------------------------------------------
__device__ __forceinline__ uint32_t h2u(float a, float b) {
    __half2 h = __floats2half2_rn(a, b);
    return *reinterpret_cast<uint32_t*>(&h);
}
__device__ __forceinline__ uint32_t smaddr(const void* p) {
    return (uint32_t)__cvta_generic_to_shared(p);
}
__device__ __forceinline__ void cp16(void* dst, const void* src) {
    asm volatile("cp.async.cg.shared.global [%0], [%1], 16;"
                 :: "r"(smaddr(dst)), "l"(src));
}
#define CP_COMMIT() asm volatile("cp.async.commit_group;")
#define CP_WAIT(n)  asm volatile("cp.async.wait_group %0;" :: "n"(n))

__device__ __forceinline__ void ldsm4(uint32_t& r0, uint32_t& r1,
                                      uint32_t& r2, uint32_t& r3, const void* p) {
    asm volatile("ldmatrix.sync.aligned.m8n8.x4.shared.b16 {%0,%1,%2,%3}, [%4];"
                 : "=r"(r0), "=r"(r1), "=r"(r2), "=r"(r3) : "r"(smaddr(p)));
}
__device__ __forceinline__ void ldsm4t(uint32_t& r0, uint32_t& r1,
                                       uint32_t& r2, uint32_t& r3, const void* p) {
    asm volatile("ldmatrix.sync.aligned.m8n8.x4.trans.shared.b16 {%0,%1,%2,%3}, [%4];"
                 : "=r"(r0), "=r"(r1), "=r"(r2), "=r"(r3) : "r"(smaddr(p)));
}
__device__ __forceinline__ void mma_h(float4& d,
    uint32_t a0, uint32_t a1, uint32_t a2, uint32_t a3,
    uint32_t b0, uint32_t b1)
{
    asm volatile(
        "mma.sync.aligned.m16n8k16.row.col.f32.f16.f16.f32 "
        "{%0,%1,%2,%3}, {%4,%5,%6,%7}, {%8,%9}, {%0,%1,%2,%3};"
        : "+f"(d.x), "+f"(d.y), "+f"(d.z), "+f"(d.w)
        : "r"(a0), "r"(a1), "r"(a2), "r"(a3), "r"(b0), "r"(b1));
}

// exp2 via FMA polynomial + exponent splice — no MUFU in the hot loop.
__device__ __forceinline__ float exp2_fast(float t) {
    t = fmaxf(t, -120.0f);
    float z = t + 12582912.0f;
    int  i = __float_as_int(z) - 0x4B400000;
    float f = t - (z - 12582912.0f);
    float p = 1.3333558e-3f;
    p = fmaf(p, f, 9.6181291e-3f);
    p = fmaf(p, f, 5.5504109e-2f);
    p = fmaf(p, f, 2.4022651e-1f);
    p = fmaf(p, f, 6.9314718e-1f);
    p = fmaf(p, f, 1.0f);
    return __int_as_float((i + 127) << 23) * p;
}

// ---------------- fp32 -> fp16 convert --------------------------------------
__global__ void __launch_bounds__(256) f2h_kernel(const float* __restrict__ in,
                                                  __half* __restrict__ out, int n4)
{
    int i = blockIdx.x * blockDim.x + threadIdx.x;
    if (i >= n4) return;
    float4 v = *(const float4*)(in + (size_t)i * 4);
    uint2 o;
    o.x = h2u(v.x, v.y);
    o.y = h2u(v.z, v.w);
    *(uint2*)(out + (size_t)i * 4) = o;
}

// ---------------- fp16 GEMM: C[m][n] = sum_k A[m][k] * W[n][k] (+bias) ------
// 128x128 tile, BK=32, 256 threads (8 warps, 2m x 4n), warp tile 64x32.
// 3-stage cp.async pipeline, ONE barrier per iteration, ldmatrix fragments.
#define GP 40
#define GTILE (128 * GP)
template<bool BIAS>
__global__ void __launch_bounds__(256) gemm_h(
    const __half* __restrict__ A, const __half* __restrict__ W,
    const float* __restrict__ bias, float* __restrict__ C,
    int M, int N, int K)
{
    extern __shared__ __half gsm[];
    __half* As = gsm;               // 3 stages x GTILE
    __half* Ws = gsm + 3 * GTILE;   // 3 stages x GTILE

    const int tid = threadIdx.x;
    const int lane = tid & 31, wid = tid >> 5;
    const int g = lane >> 2, tg = lane & 3;
    const int wm = (wid & 1) * 64;
    const int wn = (wid >> 1) * 32;
    const int mtile = blockIdx.y * 128, ntile = blockIdx.x * 128;

    const int ldr = tid >> 2;            // 0..63  (x2 passes -> 128 rows)
    const int ldc = (tid & 3) * 8;       // 0,8,16,24

    auto issue = [&](int k0, int st) {
#pragma unroll
        for (int i = 0; i < 2; i++) {
            int r = ldr + i * 64;
            cp16(&As[st * GTILE + r * GP + ldc], A + (size_t)(mtile + r) * K + k0 + ldc);
            cp16(&Ws[st * GTILE + r * GP + ldc], W + (size_t)(ntile + r) * K + k0 + ldc);
        }
        CP_COMMIT();
    };

    issue(0, 0);
    issue(32, 1);

    float4 acc[4][4];
#pragma unroll
    for (int mt = 0; mt < 4; mt++)
#pragma unroll
        for (int nt = 0; nt < 4; nt++) acc[mt][nt] = make_float4(0.f, 0.f, 0.f, 0.f);

    const int NIT = K / 32;
    const int arow = (lane & 15);
    const int acol = ((lane >> 4) & 1) * 8;
    const int brow = ((lane & 16) >> 1) + (lane & 7);
    const int bcol = (lane & 8);

    int st = 0;
    for (int it = 0; it < NIT; it++) {
        if (it == NIT - 1) { CP_WAIT(0); } else { CP_WAIT(1); }
        __syncthreads();
        // issue into stage (it+2)%3 == (it-1)%3: consumed last iter, barrier-safe
        if (it + 2 < NIT) issue((it + 2) * 32, (st + 2) % 3);
        const __half* as = As + st * GTILE;
        const __half* ws = Ws + st * GTILE;
#pragma unroll
        for (int ks = 0; ks < 2; ks++) {
            uint32_t af[4][4], bf[4][2];
#pragma unroll
            for (int mt = 0; mt < 4; mt++)
                ldsm4(af[mt][0], af[mt][1], af[mt][2], af[mt][3],
                      &as[(wm + mt * 16 + arow) * GP + ks * 16 + acol]);
#pragma unroll
            for (int p = 0; p < 2; p++)
                ldsm4(bf[2 * p][0], bf[2 * p][1], bf[2 * p + 1][0], bf[2 * p + 1][1],
                      &ws[(wn + p * 16 + brow) * GP + ks * 16 + bcol]);
#pragma unroll
            for (int mt = 0; mt < 4; mt++)
#pragma unroll
                for (int nt = 0; nt < 4; nt++)
                    mma_h(acc[mt][nt], af[mt][0], af[mt][1], af[mt][2], af[mt][3],
                          bf[nt][0], bf[nt][1]);
        }
        st = (st + 1) % 3;
    }

#pragma unroll
    for (int mt = 0; mt < 4; mt++) {
        int r0 = mtile + wm + mt * 16 + g;
#pragma unroll
        for (int nt = 0; nt < 4; nt++) {
            int col = ntile + wn + nt * 8 + 2 * tg;
            float4 v = acc[mt][nt];
            float b0v = 0.f, b1v = 0.f;
            if (BIAS) { b0v = bias[col]; b1v = bias[col + 1]; }
            float2 t0 = {v.x + b0v, v.y + b1v};
            float2 t1 = {v.z + b0v, v.w + b1v};
            *(float2*)(C + (size_t)r0 * N + col) = t0;
            *(float2*)(C + (size_t)(r0 + 8) * N + col) = t1;
        }
    }
}

// -------- fused rmsnorm + 3D RoPE + q-scale(log2e) + fp16 + transpose -------
__global__ void __launch_bounds__(256) prep_kernel(
    const float* __restrict__ qkv, const float* __restrict__ positions,
    const float* __restrict__ qn_w, const float* __restrict__ kn_w,
    __half* __restrict__ qT, __half* __restrict__ kT, __half* __restrict__ vT)
{
    int gwarp = (blockIdx.x * blockDim.x + threadIdx.x) >> 5;
    int lane  = threadIdx.x & 31;
    if (gwarp >= MROWS * NH) return;
    int h = gwarp % NH;
    int m = gwarp / NH;
    int b = m / NSEQ;
    int t = m % NSEQ;

    const float* row = qkv + (size_t)m * (3 * DIMC) + h * DH;
    float2 q = *(const float2*)(row + 2 * lane);
    float2 k = *(const float2*)(row + DIMC + 2 * lane);
    float2 v = *(const float2*)(row + 2 * DIMC + 2 * lane);

    float sq = q.x * q.x + q.y * q.y;
    float sk = k.x * k.x + k.y * k.y;
#pragma unroll
    for (int off = 16; off; off >>= 1) {
        sq += __shfl_xor_sync(0xffffffffu, sq, off);
        sk += __shfl_xor_sync(0xffffffffu, sk, off);
    }
    float rq = rsqrtf(sq * (1.0f / 64.0f) + 1e-6f);
    float rk = rsqrtf(sk * (1.0f / 64.0f) + 1e-6f);
    float2 wq = *(const float2*)(qn_w + 2 * lane);
    float2 wk = *(const float2*)(kn_w + 2 * lane);
    q.x *= rq * wq.x; q.y *= rq * wq.y;
    k.x *= rk * wk.x; k.y *= rk * wk.y;

    if (lane < 30) {                   // rope pairs: first 60 dims
        int p = lane / 10;
        int f = lane % 10;
        float pos  = positions[(size_t)m * 3 + p];
        float freq = __expf(-0.92103403719761836f * (float)f);  // 10000^(-f/10)
        float ang  = pos * freq;
        float s, c;
        __sincosf(ang, &s, &c);
        float qe = q.x * c - q.y * s, qo = q.x * s + q.y * c;
        float ke = k.x * c - k.y * s, ko = k.x * s + k.y * c;
        q.x = qe; q.y = qo; k.x = ke; k.y = ko;
    }
    q.x *= QSCALE_L2E; q.y *= QSCALE_L2E;

    size_t o = ((size_t)(b * NH + h) * NSEQ + t) * DH + 2 * lane;
    *(uint32_t*)(qT + o) = h2u(q.x, q.y);
    *(uint32_t*)(kT + o) = h2u(k.x, k.y);
    *(uint32_t*)(vT + o) = h2u(v.x, v.y);
}

// ---------------- fp16 flash-attention (base-2 softmax, register P) ---------
// 256 threads (8 warps); warp owns 16 query rows. Br=128, Bc=64, DH=64.
// 3-stage KV cp.async pipeline, one barrier per iteration. fp16 output.
#define AP 72
#define KVTILE (64 * AP)
__global__ void __launch_bounds__(256) attn_h(
    const __half* __restrict__ qT, const __half* __restrict__ kT,
    const __half* __restrict__ vT, __half* __restrict__ outh)
{
    extern __shared__ __half asm_[];
    __half* Qs = asm_;                    // 128 x AP
    __half* Ks = asm_ + 128 * AP;         // 3 stages x 64 x AP
    __half* Vs = Ks + 3 * KVTILE;         // 3 stages x 64 x AP

    const int tid = threadIdx.x, lane = tid & 31, w = tid >> 5;
    const int g = lane >> 2, tg = lane & 3;
    const int qt = blockIdx.x, bh = blockIdx.y;

    auto issue_kv = [&](int kc, int st) {
        const __half* kb = kT + ((size_t)bh * NSEQ + kc * 64) * DH;
        const __half* vb = vT + ((size_t)bh * NSEQ + kc * 64) * DH;
#pragma unroll
        for (int i = 0; i < 2; i++) {
            int idx = tid + i * 256;
            int r = idx >> 3, c = (idx & 7) * 8;
            cp16(&Ks[st * KVTILE + r * AP + c], kb + r * 64 + c);
            cp16(&Vs[st * KVTILE + r * AP + c], vb + r * 64 + c);
        }
        CP_COMMIT();
    };

    // Q tile (direct load), 128 rows
    const __half* qb = qT + ((size_t)bh * NSEQ + qt * 128) * DH;
#pragma unroll
    for (int i = 0; i < 4; i++) {
        int idx = tid + i * 256;
        int r = idx >> 3, c = (idx & 7) * 8;
        *(uint4*)&Qs[r * AP + c] = *(const uint4*)(qb + r * 64 + c);
    }

    issue_kv(0, 0);
    issue_kv(1, 1);
    __syncthreads();

    const int arow = (lane & 15);
    const int acol = ((lane >> 4) & 1) * 8;
    const int brow = ((lane & 16) >> 1) + (lane & 7);
    const int bcol = (lane & 8);

    uint32_t qa[4][4];
#pragma unroll
    for (int kt = 0; kt < 4; kt++)
        ldsm4(qa[kt][0], qa[kt][1], qa[kt][2], qa[kt][3],
              &Qs[(w * 16 + arow) * AP + kt * 16 + acol]);

    float4 accO[8];
#pragma unroll
    for (int nt = 0; nt < 8; nt++) accO[nt] = make_float4(0.f, 0.f, 0.f, 0.f);
    float m0 = -1e30f, m1 = -1e30f, l0 = 0.f, l1 = 0.f;

    int st = 0;
    for (int kc = 0; kc < 32; kc++) {
        if (kc == 31) { CP_WAIT(0); } else { CP_WAIT(1); }
        __syncthreads();
        if (kc + 2 < 32) issue_kv(kc + 2, (st + 2) % 3);
        const __half* ks = Ks + st * KVTILE;
        const __half* vs = Vs + st * KVTILE;

        // ---- S = Q @ K^T ----
        float4 s[8];
#pragma unroll
        for (int nt = 0; nt < 8; nt++) s[nt] = make_float4(0.f, 0.f, 0.f, 0.f);
#pragma unroll
        for (int kt = 0; kt < 4; kt++) {
            uint32_t kb[8][2];
#pragma unroll
            for (int p = 0; p < 4; p++)
                ldsm4(kb[2 * p][0], kb[2 * p][1], kb[2 * p + 1][0], kb[2 * p + 1][1],
                      &ks[(p * 16 + brow) * AP + kt * 16 + bcol]);
#pragma unroll
            for (int nt = 0; nt < 8; nt++)
                mma_h(s[nt], qa[kt][0], qa[kt][1], qa[kt][2], qa[kt][3],
                      kb[nt][0], kb[nt][1]);
        }

        // ---- online softmax (rows g and g+8) ----
        float rm0 = -1e30f, rm1 = -1e30f;
#pragma unroll
        for (int nt = 0; nt < 8; nt++) {
            rm0 = fmaxf(rm0, fmaxf(s[nt].x, s[nt].y));
            rm1 = fmaxf(rm1, fmaxf(s[nt].z, s[nt].w));
        }
        rm0 = fmaxf(rm0, __shfl_xor_sync(0xffffffffu, rm0, 1));
        rm0 = fmaxf(rm0, __shfl_xor_sync(0xffffffffu, rm0, 2));
        rm1 = fmaxf(rm1, __shfl_xor_sync(0xffffffffu, rm1, 1));
        rm1 = fmaxf(rm1, __shfl_xor_sync(0xffffffffu, rm1, 2));
        float nm0 = fmaxf(m0, rm0), nm1 = fmaxf(m1, rm1);
        float cr0 = exp2_fast(m0 - nm0), cr1 = exp2_fast(m1 - nm1);
        m0 = nm0; m1 = nm1;

        float sum0 = 0.f, sum1 = 0.f;
#pragma unroll
        for (int nt = 0; nt < 8; nt++) {
            s[nt].x = exp2_fast(s[nt].x - nm0);
            s[nt].y = exp2_fast(s[nt].y - nm0);
            s[nt].z = exp2_fast(s[nt].z - nm1);
            s[nt].w = exp2_fast(s[nt].w - nm1);
            sum0 += s[nt].x + s[nt].y;
            sum1 += s[nt].z + s[nt].w;
        }
        sum0 += __shfl_xor_sync(0xffffffffu, sum0, 1);
        sum0 += __shfl_xor_sync(0xffffffffu, sum0, 2);
        sum1 += __shfl_xor_sync(0xffffffffu, sum1, 1);
        sum1 += __shfl_xor_sync(0xffffffffu, sum1, 2);
        l0 = l0 * cr0 + sum0;
        l1 = l1 * cr1 + sum1;
#pragma unroll
        for (int nt = 0; nt < 8; nt++) {
            accO[nt].x *= cr0; accO[nt].y *= cr0;
            accO[nt].z *= cr1; accO[nt].w *= cr1;
        }

        // ---- P fragments directly in registers (C-frag layout == A-frag) ----
        uint32_t pa[4][4];
#pragma unroll
        for (int j = 0; j < 4; j++) {
            pa[j][0] = h2u(s[2 * j].x,     s[2 * j].y);
            pa[j][1] = h2u(s[2 * j].z,     s[2 * j].w);
            pa[j][2] = h2u(s[2 * j + 1].x, s[2 * j + 1].y);
            pa[j][3] = h2u(s[2 * j + 1].z, s[2 * j + 1].w);
        }

        // ---- O += P @ V ----
#pragma unroll
        for (int kt = 0; kt < 4; kt++) {
            uint32_t vb[8][2];
#pragma unroll
            for (int q4 = 0; q4 < 4; q4++)
                ldsm4t(vb[2 * q4][0], vb[2 * q4][1], vb[2 * q4 + 1][0], vb[2 * q4 + 1][1],
                       &vs[(kt * 16 + arow) * AP + q4 * 16 + acol]);
#pragma unroll
            for (int nt = 0; nt < 8; nt++)
                mma_h(accO[nt], pa[kt][0], pa[kt][1], pa[kt][2], pa[kt][3],
                      vb[nt][0], vb[nt][1]);
        }
        st = (st + 1) % 3;
    }

    // epilogue: fp16 output [b*N + q][h*64 + d]  (feeds proj GEMM directly)
    const int b = bh / NH, h = bh % NH;
    const int r0 = qt * 128 + w * 16 + g;
    const float i0 = 1.f / l0, i1 = 1.f / l1;
#pragma unroll
    for (int nt = 0; nt < 8; nt++) {
        int col = h * 64 + nt * 8 + 2 * tg;
        *(uint32_t*)(outh + (size_t)(b * NSEQ + r0) * DIMC + col) =
            h2u(accO[nt].x * i0, accO[nt].y * i0);
        *(uint32_t*)(outh + (size_t)(b * NSEQ + r0 + 8) * DIMC + col) =
            h2u(accO[nt].z * i1, accO[nt].w * i1);
    }
}

// ---------------- launch ----------------------------------------------------
extern "C" void kernel_launch(void* const* d_in, const int* in_sizes, int n_in,
                              void* d_out, int out_size)
{
    (void)in_sizes; (void)n_in; (void)out_size;
    const float* x         = (const float*)d_in[0];
    const float* positions = (const float*)d_in[1];
    const float* qkv_w     = (const float*)d_in[2];
    const float* proj_w    = (const float*)d_in[3];
    const float* proj_b    = (const float*)d_in[4];
    const float* qn_w      = (const float*)d_in[5];
    const float* kn_w      = (const float*)d_in[6];
    float* out = (float*)d_out;

    float *qkv;
    __half *xh, *qkvwh, *projwh, *atth, *q, *k, *v;
    cudaGetSymbolAddress((void**)&qkv,    g_qkv);
    cudaGetSymbolAddress((void**)&xh,     g_xh);
    cudaGetSymbolAddress((void**)&qkvwh,  g_qkvwh);
    cudaGetSymbolAddress((void**)&projwh, g_projwh);
    cudaGetSymbolAddress((void**)&atth,   g_atth);
    cudaGetSymbolAddress((void**)&q,      g_q);
    cudaGetSymbolAddress((void**)&k,      g_k);
    cudaGetSymbolAddress((void**)&v,      g_v);

    const int gemm_smem = 3 * 2 * GTILE * (int)sizeof(__half);            // 61440
    const int attn_smem = (128 * AP + 6 * KVTILE) * (int)sizeof(__half);  // 73728
    cudaFuncSetAttribute(gemm_h<false>,
                         cudaFuncAttributeMaxDynamicSharedMemorySize, gemm_smem);
    cudaFuncSetAttribute(gemm_h<true>,
                         cudaFuncAttributeMaxDynamicSharedMemorySize, gemm_smem);
    cudaFuncSetAttribute(attn_h,
                         cudaFuncAttributeMaxDynamicSharedMemorySize, attn_smem);

    // 0) convert inputs to fp16
    {
        int n4;
        n4 = MROWS * DIMC / 4;
        f2h_kernel<<<(n4 + 255) / 256, 256>>>(x, xh, n4);
        n4 = 3 * DIMC * DIMC / 4;
        f2h_kernel<<<(n4 + 255) / 256, 256>>>(qkv_w, qkvwh, n4);
        n4 = DIMC * DIMC / 4;
        f2h_kernel<<<(n4 + 255) / 256, 256>>>(proj_w, projwh, n4);
    }

    // 1) qkv = x @ qkv_w^T    [4096, 2304] (fp32 out)
    gemm_h<false><<<dim3(2304 / 128, MROWS / 128), 256, gemm_smem>>>(
        xh, qkvwh, nullptr, qkv, MROWS, 3 * DIMC, DIMC);

    // 2) rmsnorm + rope + scale + fp16 + transpose to [BH, N, DH]
    prep_kernel<<<(MROWS * NH * 32) / 256, 256>>>(
        qkv, positions, qn_w, kn_w, q, k, v);

    // 3) attention (fp16 tensor cores, base-2 softmax, fp16 out)
    attn_h<<<dim3(NSEQ / 128, BHN), 256, attn_smem>>>(q, k, v, atth);

    // 4) out = att @ proj_w^T + proj_b
    gemm_h<true><<<dim3(DIMC / 128, MROWS / 128), 256, gemm_smem>>>(
        atth, projwh, proj_b, out, MROWS, DIMC, DIMC);
}

// round 8
// speedup vs baseline: 7.9965x; 1.0778x over previous
#include <cuda_runtime.h>
#include <cuda_fp16.h>
#include <math.h>
#include <stdint.h>

#define BB 2
#define NSEQ 2048
#define DIMC 768
#define NH 12
#define DH 64
#define BHN (BB*NH)
#define MROWS (BB*NSEQ)
// 0.125 * log2(e): softmax done in base-2
#define QSCALE_L2E 0.18033688011112042f
// static softmax offset: |scores| <= 64*0.125*log2e = 11.54 < 12 (rmsnorm + rotation)
#define SOFF 12.0f

// ---------------- scratch (static device globals; no allocation) -------------
__device__ float  g_qkv[(size_t)MROWS * 3 * DIMC];          // fp32 qkv
__device__ __half g_xh[(size_t)MROWS * DIMC];
__device__ __half g_qkvwh[(size_t)3 * DIMC * DIMC];
__device__ __half g_projwh[(size_t)DIMC * DIMC];
__device__ __half g_atth[(size_t)MROWS * DIMC];
__device__ __half g_q[(size_t)BHN * NSEQ * DH];
__device__ __half g_k[(size_t)BHN * NSEQ * DH];
__device__ __half g_v[(size_t)BHN * NSEQ * DH];

// ---------------- helpers ---------------------------------------------------
__device__ __forceinline__ uint32_t h2u(float a, float b) {
    __half2 h = __floats2half2_rn(a, b);
    return *reinterpret_cast<uint32_t*>(&h);
}
__device__ __forceinline__ uint32_t smaddr(const void* p) {
    return (uint32_t)__cvta_generic_to_shared(p);
}
__device__ __forceinline__ void cp16(void* dst, const void* src) {
    asm volatile("cp.async.cg.shared.global [%0], [%1], 16;"
                 :: "r"(smaddr(dst)), "l"(src));
}
#define CP_COMMIT() asm volatile("cp.async.commit_group;")
#define CP_WAIT(n)  asm volatile("cp.async.wait_group %0;" :: "n"(n))

__device__ __forceinline__ void ldsm4(uint32_t& r0, uint32_t& r1,
                                      uint32_t& r2, uint32_t& r3, const void* p) {
    asm volatile("ldmatrix.sync.aligned.m8n8.x4.shared.b16 {%0,%1,%2,%3}, [%4];"
                 : "=r"(r0), "=r"(r1), "=r"(r2), "=r"(r3) : "r"(smaddr(p)));
}
__device__ __forceinline__ void ldsm4t(uint32_t& r0, uint32_t& r1,
                                       uint32_t& r2, uint32_t& r3, const void* p) {
    asm volatile("ldmatrix.sync.aligned.m8n8.x4.trans.shared.b16 {%0,%1,%2,%3}, [%4];"
                 : "=r"(r0), "=r"(r1), "=r"(r2), "=r"(r3) : "r"(smaddr(p)));
}
__device__ __forceinline__ void mma_h(float4& d,
    uint32_t a0, uint32_t a1, uint32_t a2, uint32_t a3,
    uint32_t b0, uint32_t b1)
{
    asm volatile(
        "mma.sync.aligned.m16n8k16.row.col.f32.f16.f16.f32 "
        "{%0,%1,%2,%3}, {%4,%5,%6,%7}, {%8,%9}, {%0,%1,%2,%3};"
        : "+f"(d.x), "+f"(d.y), "+f"(d.z), "+f"(d.w)
        : "r"(a0), "r"(a1), "r"(a2), "r"(a3), "r"(b0), "r"(b1));
}

// exp2 via FMA polynomial + exponent splice — no MUFU in the hot loop.
__device__ __forceinline__ float exp2_fast(float t) {
    t = fmaxf(t, -120.0f);
    float z = t + 12582912.0f;
    int  i = __float_as_int(z) - 0x4B400000;
    float f = t - (z - 12582912.0f);
    float p = 1.3333558e-3f;
    p = fmaf(p, f, 9.6181291e-3f);
    p = fmaf(p, f, 5.5504109e-2f);
    p = fmaf(p, f, 2.4022651e-1f);
    p = fmaf(p, f, 6.9314718e-1f);
    p = fmaf(p, f, 1.0f);
    return __int_as_float((i + 127) << 23) * p;
}

// ---------------- fp32 -> fp16 convert --------------------------------------
__global__ void __launch_bounds__(256) f2h_kernel(const float* __restrict__ in,
                                                  __half* __restrict__ out, int n4)
{
    int i = blockIdx.x * blockDim.x + threadIdx.x;
    if (i >= n4) return;
    float4 v = *(const float4*)(in + (size_t)i * 4);
    uint2 o;
    o.x = h2u(v.x, v.y);
    o.y = h2u(v.z, v.w);
    *(uint2*)(out + (size_t)i * 4) = o;
}

// ---------------- fp16 GEMM: C[m][n] = sum_k A[m][k] * W[n][k] (+bias) ------
// CTA tile 128x256, BK=32, 256 threads (8 warps, 2m x 4n), warp tile 64x64.
// 3-stage cp.async pipeline, one barrier per iteration, ldmatrix fragments.
#define GP 40
#define GATILE (128 * GP)
#define GBTILE (256 * GP)
#define GEMM_SMEM ((3 * GATILE + 3 * GBTILE) * (int)sizeof(__half))   // 92160
template<bool BIAS>
__global__ void __launch_bounds__(256) gemm_h(
    const __half* __restrict__ A, const __half* __restrict__ W,
    const float* __restrict__ bias, float* __restrict__ C,
    int M, int N, int K)
{
    extern __shared__ __half gsm[];
    __half* As = gsm;                  // 3 stages x GATILE
    __half* Ws = gsm + 3 * GATILE;     // 3 stages x GBTILE

    const int tid = threadIdx.x;
    const int lane = tid & 31, wid = tid >> 5;
    const int g = lane >> 2, tg = lane & 3;
    const int wm = (wid & 1) * 64;
    const int wn = (wid >> 1) * 64;
    const int mtile = blockIdx.y * 128, ntile = blockIdx.x * 256;

    const int ldr = tid >> 2;            // 0..63
    const int ldc = (tid & 3) * 8;       // 0,8,16,24

    auto issue = [&](int k0, int st) {
#pragma unroll
        for (int i = 0; i < 2; i++) {      // A: 128 rows
            int r = ldr + i * 64;
            cp16(&As[st * GATILE + r * GP + ldc], A + (size_t)(mtile + r) * K + k0 + ldc);
        }
#pragma unroll
        for (int i = 0; i < 4; i++) {      // B: 256 rows
            int r = ldr + i * 64;
            cp16(&Ws[st * GBTILE + r * GP + ldc], W + (size_t)(ntile + r) * K + k0 + ldc);
        }
        CP_COMMIT();
    };

    issue(0, 0);
    issue(32, 1);

    float4 acc[4][8];
#pragma unroll
    for (int mt = 0; mt < 4; mt++)
#pragma unroll
        for (int nt = 0; nt < 8; nt++) acc[mt][nt] = make_float4(0.f, 0.f, 0.f, 0.f);

    const int NIT = K / 32;
    const int arow = (lane & 15);
    const int acol = ((lane >> 4) & 1) * 8;
    const int brow = ((lane & 16) >> 1) + (lane & 7);
    const int bcol = (lane & 8);

    int st = 0;
    for (int it = 0; it < NIT; it++) {
        if (it == NIT - 1) { CP_WAIT(0); } else { CP_WAIT(1); }
        __syncthreads();
        if (it + 2 < NIT) issue((it + 2) * 32, (st + 2) % 3);
        const __half* as = As + st * GATILE;
        const __half* ws = Ws + st * GBTILE;
#pragma unroll
        for (int ks = 0; ks < 2; ks++) {
            uint32_t af[4][4], bf[8][2];
#pragma unroll
            for (int mt = 0; mt < 4; mt++)
                ldsm4(af[mt][0], af[mt][1], af[mt][2], af[mt][3],
                      &as[(wm + mt * 16 + arow) * GP + ks * 16 + acol]);
#pragma unroll
            for (int p = 0; p < 4; p++)
                ldsm4(bf[2 * p][0], bf[2 * p][1], bf[2 * p + 1][0], bf[2 * p + 1][1],
                      &ws[(wn + p * 16 + brow) * GP + ks * 16 + bcol]);
#pragma unroll
            for (int mt = 0; mt < 4; mt++)
#pragma unroll
                for (int nt = 0; nt < 8; nt++)
                    mma_h(acc[mt][nt], af[mt][0], af[mt][1], af[mt][2], af[mt][3],
                          bf[nt][0], bf[nt][1]);
        }
        st = (st + 1) % 3;
    }

#pragma unroll
    for (int mt = 0; mt < 4; mt++) {
        int r0 = mtile + wm + mt * 16 + g;
#pragma unroll
        for (int nt = 0; nt < 8; nt++) {
            int col = ntile + wn + nt * 8 + 2 * tg;
            float4 v = acc[mt][nt];
            float b0v = 0.f, b1v = 0.f;
            if (BIAS) { b0v = bias[col]; b1v = bias[col + 1]; }
            float2 t0 = {v.x + b0v, v.y + b1v};
            float2 t1 = {v.z + b0v, v.w + b1v};
            *(float2*)(C + (size_t)r0 * N + col) = t0;
            *(float2*)(C + (size_t)(r0 + 8) * N + col) = t1;
        }
    }
}

// -------- fused rmsnorm + 3D RoPE + q-scale(log2e) + fp16 + transpose -------
__global__ void __launch_bounds__(256) prep_kernel(
    const float* __restrict__ qkv, const float* __restrict__ positions,
    const float* __restrict__ qn_w, const float* __restrict__ kn_w,
    __half* __restrict__ qT, __half* __restrict__ kT, __half* __restrict__ vT)
{
    int gwarp = (blockIdx.x * blockDim.x + threadIdx.x) >> 5;
    int lane  = threadIdx.x & 31;
    if (gwarp >= MROWS * NH) return;
    int h = gwarp % NH;
    int m = gwarp / NH;
    int b = m / NSEQ;
    int t = m % NSEQ;

    const float* row = qkv + (size_t)m * (3 * DIMC) + h * DH;
    float2 q = *(const float2*)(row + 2 * lane);
    float2 k = *(const float2*)(row + DIMC + 2 * lane);
    float2 v = *(const float2*)(row + 2 * DIMC + 2 * lane);

    float sq = q.x * q.x + q.y * q.y;
    float sk = k.x * k.x + k.y * k.y;
#pragma unroll
    for (int off = 16; off; off >>= 1) {
        sq += __shfl_xor_sync(0xffffffffu, sq, off);
        sk += __shfl_xor_sync(0xffffffffu, sk, off);
    }
    float rq = rsqrtf(sq * (1.0f / 64.0f) + 1e-6f);
    float rk = rsqrtf(sk * (1.0f / 64.0f) + 1e-6f);
    float2 wq = *(const float2*)(qn_w + 2 * lane);
    float2 wk = *(const float2*)(kn_w + 2 * lane);
    q.x *= rq * wq.x; q.y *= rq * wq.y;
    k.x *= rk * wk.x; k.y *= rk * wk.y;

    if (lane < 30) {                   // rope pairs: first 60 dims
        int p = lane / 10;
        int f = lane % 10;
        float pos  = positions[(size_t)m * 3 + p];
        float freq = __expf(-0.92103403719761836f * (float)f);  // 10000^(-f/10)
        float ang  = pos * freq;
        float s, c;
        __sincosf(ang, &s, &c);
        float qe = q.x * c - q.y * s, qo = q.x * s + q.y * c;
        float ke = k.x * c - k.y * s, ko = k.x * s + k.y * c;
        q.x = qe; q.y = qo; k.x = ke; k.y = ko;
    }
    q.x *= QSCALE_L2E; q.y *= QSCALE_L2E;

    size_t o = ((size_t)(b * NH + h) * NSEQ + t) * DH + 2 * lane;
    *(uint32_t*)(qT + o) = h2u(q.x, q.y);
    *(uint32_t*)(kT + o) = h2u(k.x, k.y);
    *(uint32_t*)(vT + o) = h2u(v.x, v.y);
}

// ---------------- fp16 flash-attention (static-offset base-2 softmax) -------
// 256 threads (8 warps); warp owns 16 query rows. Br=128, Bc=64, DH=64.
// Scores are bounded (rmsnorm -> |s| <= 11.54 base-2), so softmax uses a fixed
// offset: no running max, no correction factors, no per-iter reductions.
#define AP 72
#define KVTILE (64 * AP)
__global__ void __launch_bounds__(256) attn_h(
    const __half* __restrict__ qT, const __half* __restrict__ kT,
    const __half* __restrict__ vT, __half* __restrict__ outh)
{
    extern __shared__ __half asm_[];
    __half* Qs = asm_;                    // 128 x AP
    __half* Ks = asm_ + 128 * AP;         // 3 stages x 64 x AP
    __half* Vs = Ks + 3 * KVTILE;         // 3 stages x 64 x AP

    const int tid = threadIdx.x, lane = tid & 31, w = tid >> 5;
    const int g = lane >> 2, tg = lane & 3;
    const int qt = blockIdx.x, bh = blockIdx.y;

    auto issue_kv = [&](int kc, int st) {
        const __half* kb = kT + ((size_t)bh * NSEQ + kc * 64) * DH;
        const __half* vb = vT + ((size_t)bh * NSEQ + kc * 64) * DH;
#pragma unroll
        for (int i = 0; i < 2; i++) {
            int idx = tid + i * 256;
            int r = idx >> 3, c = (idx & 7) * 8;
            cp16(&Ks[st * KVTILE + r * AP + c], kb + r * 64 + c);
            cp16(&Vs[st * KVTILE + r * AP + c], vb + r * 64 + c);
        }
        CP_COMMIT();
    };

    const __half* qb = qT + ((size_t)bh * NSEQ + qt * 128) * DH;
#pragma unroll
    for (int i = 0; i < 4; i++) {
        int idx = tid + i * 256;
        int r = idx >> 3, c = (idx & 7) * 8;
        *(uint4*)&Qs[r * AP + c] = *(const uint4*)(qb + r * 64 + c);
    }

    issue_kv(0, 0);
    issue_kv(1, 1);
    __syncthreads();

    const int arow = (lane & 15);
    const int acol = ((lane >> 4) & 1) * 8;
    const int brow = ((lane & 16) >> 1) + (lane & 7);
    const int bcol = (lane & 8);

    uint32_t qa[4][4];
#pragma unroll
    for (int kt = 0; kt < 4; kt++)
        ldsm4(qa[kt][0], qa[kt][1], qa[kt][2], qa[kt][3],
              &Qs[(w * 16 + arow) * AP + kt * 16 + acol]);

    float4 accO[8];
#pragma unroll
    for (int nt = 0; nt < 8; nt++) accO[nt] = make_float4(0.f, 0.f, 0.f, 0.f);
    float l0 = 0.f, l1 = 0.f;

    int st = 0;
    for (int kc = 0; kc < 32; kc++) {
        if (kc == 31) { CP_WAIT(0); } else { CP_WAIT(1); }
        __syncthreads();
        if (kc + 2 < 32) issue_kv(kc + 2, (st + 2) % 3);
        const __half* ks = Ks + st * KVTILE;
        const __half* vs = Vs + st * KVTILE;

        // ---- S = Q @ K^T ----
        float4 s[8];
#pragma unroll
        for (int nt = 0; nt < 8; nt++) s[nt] = make_float4(0.f, 0.f, 0.f, 0.f);
#pragma unroll
        for (int kt = 0; kt < 4; kt++) {
            uint32_t kb[8][2];
#pragma unroll
            for (int p = 0; p < 4; p++)
                ldsm4(kb[2 * p][0], kb[2 * p][1], kb[2 * p + 1][0], kb[2 * p + 1][1],
                      &ks[(p * 16 + brow) * AP + kt * 16 + bcol]);
#pragma unroll
            for (int nt = 0; nt < 8; nt++)
                mma_h(s[nt], qa[kt][0], qa[kt][1], qa[kt][2], qa[kt][3],
                      kb[nt][0], kb[nt][1]);
        }

        // ---- static-offset softmax: p = 2^(s - SOFF) ----
        uint32_t pa[4][4];
#pragma unroll
        for (int nt = 0; nt < 8; nt++) {
            s[nt].x = exp2_fast(s[nt].x - SOFF);
            s[nt].y = exp2_fast(s[nt].y - SOFF);
            s[nt].z = exp2_fast(s[nt].z - SOFF);
            s[nt].w = exp2_fast(s[nt].w - SOFF);
            l0 += s[nt].x + s[nt].y;
            l1 += s[nt].z + s[nt].w;
        }
#pragma unroll
        for (int j = 0; j < 4; j++) {
            pa[j][0] = h2u(s[2 * j].x,     s[2 * j].y);
            pa[j][1] = h2u(s[2 * j].z,     s[2 * j].w);
            pa[j][2] = h2u(s[2 * j + 1].x, s[2 * j + 1].y);
            pa[j][3] = h2u(s[2 * j + 1].z, s[2 * j + 1].w);
        }

        // ---- O += P @ V ----
#pragma unroll
        for (int kt = 0; kt < 4; kt++) {
            uint32_t vb[8][2];
#pragma unroll
            for (int q4 = 0; q4 < 4; q4++)
                ldsm4t(vb[2 * q4][0], vb[2 * q4][1], vb[2 * q4 + 1][0], vb[2 * q4 + 1][1],
                       &vs[(kt * 16 + arow) * AP + q4 * 16 + acol]);
#pragma unroll
            for (int nt = 0; nt < 8; nt++)
                mma_h(accO[nt], pa[kt][0], pa[kt][1], pa[kt][2], pa[kt][3],
                      vb[nt][0], vb[nt][1]);
        }
        st = (st + 1) % 3;
    }

    // one reduction at the end: combine tg lanes (cols) within each row
    l0 += __shfl_xor_sync(0xffffffffu, l0, 1);
    l0 += __shfl_xor_sync(0xffffffffu, l0, 2);
    l1 += __shfl_xor_sync(0xffffffffu, l1, 1);
    l1 += __shfl_xor_sync(0xffffffffu, l1, 2);

    const int b = bh / NH, h = bh % NH;
    const int r0 = qt * 128 + w * 16 + g;
    const float i0 = 1.f / l0, i1 = 1.f / l1;
#pragma unroll
    for (int nt = 0; nt < 8; nt++) {
        int col = h * 64 + nt * 8 + 2 * tg;
        *(uint32_t*)(outh + (size_t)(b * NSEQ + r0) * DIMC + col) =
            h2u(accO[nt].x * i0, accO[nt].y * i0);
        *(uint32_t*)(outh + (size_t)(b * NSEQ + r0 + 8) * DIMC + col) =
            h2u(accO[nt].z * i1, accO[nt].w * i1);
    }
}

// ---------------- launch ----------------------------------------------------
extern "C" void kernel_launch(void* const* d_in, const int* in_sizes, int n_in,
                              void* d_out, int out_size)
{
    (void)in_sizes; (void)n_in; (void)out_size;
    const float* x         = (const float*)d_in[0];
    const float* positions = (const float*)d_in[1];
    const float* qkv_w     = (const float*)d_in[2];
    const float* proj_w    = (const float*)d_in[3];
    const float* proj_b    = (const float*)d_in[4];
    const float* qn_w      = (const float*)d_in[5];
    const float* kn_w      = (const float*)d_in[6];
    float* out = (float*)d_out;

    float *qkv;
    __half *xh, *qkvwh, *projwh, *atth, *q, *k, *v;
    cudaGetSymbolAddress((void**)&qkv,    g_qkv);
    cudaGetSymbolAddress((void**)&xh,     g_xh);
    cudaGetSymbolAddress((void**)&qkvwh,  g_qkvwh);
    cudaGetSymbolAddress((void**)&projwh, g_projwh);
    cudaGetSymbolAddress((void**)&atth,   g_atth);
    cudaGetSymbolAddress((void**)&q,      g_q);
    cudaGetSymbolAddress((void**)&k,      g_k);
    cudaGetSymbolAddress((void**)&v,      g_v);

    const int attn_smem = (128 * AP + 6 * KVTILE) * (int)sizeof(__half);  // 73728
    cudaFuncSetAttribute(gemm_h<false>,
                         cudaFuncAttributeMaxDynamicSharedMemorySize, GEMM_SMEM);
    cudaFuncSetAttribute(gemm_h<true>,
                         cudaFuncAttributeMaxDynamicSharedMemorySize, GEMM_SMEM);
    cudaFuncSetAttribute(attn_h,
                         cudaFuncAttributeMaxDynamicSharedMemorySize, attn_smem);

    // 0) convert inputs to fp16
    {
        int n4;
        n4 = MROWS * DIMC / 4;
        f2h_kernel<<<(n4 + 255) / 256, 256>>>(x, xh, n4);
        n4 = 3 * DIMC * DIMC / 4;
        f2h_kernel<<<(n4 + 255) / 256, 256>>>(qkv_w, qkvwh, n4);
        n4 = DIMC * DIMC / 4;
        f2h_kernel<<<(n4 + 255) / 256, 256>>>(proj_w, projwh, n4);
    }

    // 1) qkv = x @ qkv_w^T    [4096, 2304] (fp32 out)
    gemm_h<false><<<dim3(2304 / 256, MROWS / 128), 256, GEMM_SMEM>>>(
        xh, qkvwh, nullptr, qkv, MROWS, 3 * DIMC, DIMC);

    // 2) rmsnorm + rope + scale + fp16 + transpose to [BH, N, DH]
    prep_kernel<<<(MROWS * NH * 32) / 256, 256>>>(
        qkv, positions, qn_w, kn_w, q, k, v);

    // 3) attention (fp16 tensor cores, static-offset base-2 softmax)
    attn_h<<<dim3(NSEQ / 128, BHN), 256, attn_smem>>>(q, k, v, atth);

    // 4) out = att @ proj_w^T + proj_b
    gemm_h<true><<<dim3(DIMC / 256, MROWS / 128), 256, GEMM_SMEM>>>(
        atth, projwh, proj_b, out, MROWS, DIMC, DIMC);
}